// round 10
// baseline (speedup 1.0000x reference)
#include <cuda_runtime.h>
#include <float.h>

#define BB 32
#define QQ 300
#define NCLS 92
#define MM 50
#define NP (BB*QQ)      // 9600 pred rows
#define NT (BB*MM)      // 1600 target cols
#define M1 300          // m (columns in hungarian)
#define N1 50           // n (rows in hungarian)

// Normalized softmax probabilities, 9600 x 92 (3.53 MB scratch)
__device__ float g_probs[NP * NCLS];
// Dense per-batch diagonal cost tiles, layout [b][i(target)][j(pred)] = 32*50*300
__device__ float g_diag[BB * N1 * M1];

// ---------------------------------------------------------------------------
// Kernel A: row softmax of logits. One warp per row.
// ---------------------------------------------------------------------------
__global__ void softmax_kernel(const float* __restrict__ logits) {
    int warp = (blockIdx.x * blockDim.x + threadIdx.x) >> 5;
    int lane = threadIdx.x & 31;
    if (warp >= NP) return;
    const float* row = logits + (size_t)warp * NCLS;
    float x0 = row[lane];
    float x1 = row[lane + 32];
    float x2 = (lane < NCLS - 64) ? row[lane + 64] : -FLT_MAX;
    float mx = fmaxf(fmaxf(x0, x1), x2);
    #pragma unroll
    for (int o = 16; o; o >>= 1) mx = fmaxf(mx, __shfl_xor_sync(0xffffffffu, mx, o));
    float e0 = __expf(x0 - mx), e1 = __expf(x1 - mx);
    float e2 = (lane < NCLS - 64) ? __expf(x2 - mx) : 0.f;
    float s = e0 + e1 + e2;
    #pragma unroll
    for (int o = 16; o; o >>= 1) s += __shfl_xor_sync(0xffffffffu, s, o);
    float inv = __fdividef(1.f, s);
    float* prow = g_probs + (size_t)warp * NCLS;
    prow[lane] = e0 * inv;
    prow[lane + 32] = e1 * inv;
    if (lane < NCLS - 64) prow[lane + 64] = e2 * inv;
}

// ---------------------------------------------------------------------------
// Kernel B: full cross cost matrix C[9600][1600] + diagonal sidecar.
// Block (16,16): 16 target-quads (64 targets) x 16 preds. Each thread:
// 1 pred x 4 consecutive targets -> 4 independent chains, one float4 store.
// ---------------------------------------------------------------------------
__global__ void __launch_bounds__(256)
cost_kernel(const float* __restrict__ pred_boxes,
            const int*   __restrict__ tgt_labels,
            const float* __restrict__ tgt_boxes,
            float* __restrict__ Cout) {
    __shared__ float s_probs[16 * NCLS];
    __shared__ float s_pc[16][4];    // pred cxcywh
    __shared__ float s_px[16][4];    // pred xyxy
    __shared__ float s_pa[16];       // pred area
    __shared__ float s_tc[64][4];    // tgt cxcywh
    __shared__ float s_tx[64][4];    // tgt xyxy
    __shared__ float s_ta[64];       // tgt area
    __shared__ int   s_tl[64];       // tgt label
    __shared__ int   s_tb[64];       // tgt batch

    int tid = threadIdx.y * 16 + threadIdx.x;
    int t0 = blockIdx.x * 64;
    int p0 = blockIdx.y * 16;

    for (int i = tid; i < 16 * NCLS; i += 256) {
        int pp = i / NCLS, c = i - pp * NCLS;
        s_probs[pp * NCLS + c] = g_probs[(size_t)(p0 + pp) * NCLS + c];
    }
    if (tid < 16) {
        const float* b = pred_boxes + (size_t)(p0 + tid) * 4;
        float cx = b[0], cy = b[1], w = b[2], h = b[3];
        s_pc[tid][0] = cx; s_pc[tid][1] = cy; s_pc[tid][2] = w; s_pc[tid][3] = h;
        float x0 = cx - 0.5f * w, y0 = cy - 0.5f * h;
        float x1 = cx + 0.5f * w, y1 = cy + 0.5f * h;
        s_px[tid][0] = x0; s_px[tid][1] = y0; s_px[tid][2] = x1; s_px[tid][3] = y1;
        s_pa[tid] = (x1 - x0) * (y1 - y0);
    }
    if (tid < 64) {
        int gt = t0 + tid;
        const float* b = tgt_boxes + (size_t)gt * 4;
        float cx = b[0], cy = b[1], w = b[2], h = b[3];
        s_tc[tid][0] = cx; s_tc[tid][1] = cy; s_tc[tid][2] = w; s_tc[tid][3] = h;
        float x0 = cx - 0.5f * w, y0 = cy - 0.5f * h;
        float x1 = cx + 0.5f * w, y1 = cy + 0.5f * h;
        s_tx[tid][0] = x0; s_tx[tid][1] = y0; s_tx[tid][2] = x1; s_tx[tid][3] = y1;
        s_ta[tid] = (x1 - x0) * (y1 - y0);
        s_tl[tid] = tgt_labels[gt];
        s_tb[tid] = gt / MM;
    }
    __syncthreads();

    int pp = threadIdx.y;
    int qx = threadIdx.x;
    int gp = p0 + pp;
    int bp = gp / QQ;
    int jloc = gp - bp * QQ;

    float pcx = s_pc[pp][0], pcy = s_pc[pp][1], pw = s_pc[pp][2], ph = s_pc[pp][3];
    float ax0 = s_px[pp][0], ay0 = s_px[pp][1], ax1 = s_px[pp][2], ay1 = s_px[pp][3];
    float areaA = s_pa[pp];
    const float* prow = s_probs + pp * NCLS;

    float4 res;
    float* r = (float*)&res;
    #pragma unroll
    for (int e = 0; e < 4; e++) {
        int t = 4 * qx + e;
        float cc = -prow[s_tl[t]];
        float cb = fabsf(pcx - s_tc[t][0]) + fabsf(pcy - s_tc[t][1])
                 + fabsf(pw  - s_tc[t][2]) + fabsf(ph  - s_tc[t][3]);
        float bx0 = s_tx[t][0], by0 = s_tx[t][1], bx1 = s_tx[t][2], by1 = s_tx[t][3];
        float iw = fmaxf(fminf(ax1, bx1) - fmaxf(ax0, bx0), 0.f);
        float ih = fmaxf(fminf(ay1, by1) - fmaxf(ay0, by0), 0.f);
        float inter = iw * ih;
        float uni = areaA + s_ta[t] - inter;
        float iou = __fdividef(inter, uni);
        float ew = fmaxf(ax1, bx1) - fminf(ax0, bx0);   // always >= 0
        float eh = fmaxf(ay1, by1) - fminf(ay0, by0);
        float r2 = __fdividef(uni, ew * eh);
        float c = cc + 5.0f * cb - 2.0f * iou - 2.0f * r2 + 2.0f;
        r[e] = c;
        int bt = s_tb[t];
        if (bt == bp) {
            int iloc = t0 + t - bt * MM;
            g_diag[(bp * N1 + iloc) * M1 + jloc] = c;
        }
    }
    *(float4*)(Cout + (size_t)gp * NT + t0 + 4 * qx) = res;
}

// ---------------------------------------------------------------------------
// Kernel C: warp-level Jonker-Volgenant with greedy dual initialization.
// Loads compact g_diag (coalesced, L2-hot). Solve on warp 0 only.
// ---------------------------------------------------------------------------
__global__ void hungarian_kernel(float* __restrict__ out) {
    extern __shared__ float smem[];
    float* cost = smem;                 // 50*300
    float* u    = cost + N1 * M1;       // 51
    int*   p    = (int*)(u + (N1 + 1)); // 301
    int*   way  = p + (M1 + 1);         // 300
    int*   pend = way + M1;             // 50
    int*   qrow = pend + N1;            // 50
    __shared__ int s_npend;

    int b = blockIdx.x;
    int tid = threadIdx.x;

    const float* gd = g_diag + (size_t)b * N1 * M1;
    for (int idx = tid; idx < N1 * M1; idx += 256) cost[idx] = gd[idx];
    for (int idx = tid; idx < N1 + 1; idx += 256) u[idx] = 0.f;
    for (int idx = tid; idx <= M1; idx += 256) p[idx] = -1;
    if (tid == 0) s_npend = 0;
    __syncthreads();
    if (tid >= 32) return;   // warp 0 solves alone

    int lane = tid;
    float v_r[10], minv_r[10];
    #pragma unroll
    for (int k = 0; k < 10; k++) v_r[k] = 0.f;

    // ---- greedy init: u[i] = row min; assign row to argmin col if free ----
    for (int i = 0; i < N1; ++i) {
        unsigned long long local = ~0ull;
        #pragma unroll
        for (int k = 0; k < 10; k++) {
            int j = lane + 32 * k;
            if (j < M1) {
                unsigned bits = __float_as_uint(cost[i * M1 + j]);
                unsigned key = (bits & 0x80000000u) ? ~bits : (bits | 0x80000000u);
                unsigned long long cand = ((unsigned long long)key << 32) | (unsigned)j;
                if (cand < local) local = cand;
            }
        }
        #pragma unroll
        for (int o = 16; o; o >>= 1) {
            unsigned long long oth = __shfl_xor_sync(0xffffffffu, local, o);
            if (oth < local) local = oth;
        }
        if (lane == 0) {
            int jstar = (int)(local & 0xffffffffu);
            unsigned key = (unsigned)(local >> 32);
            unsigned bits = (key & 0x80000000u) ? (key ^ 0x80000000u) : ~key;
            u[i] = __uint_as_float(bits);
            if (p[jstar] == -1) p[jstar] = i;
            else { pend[s_npend] = i; s_npend = s_npend + 1; }
        }
        __syncwarp();
    }
    int npend = s_npend;

    // ---- Dijkstra augmenting paths for the few unassigned rows ----
    for (int t = 0; t < npend; ++t) {
        int irow = pend[t];
        if (lane == 0) p[M1] = irow;
        #pragma unroll
        for (int k = 0; k < 10; k++) minv_r[k] = FLT_MAX;
        unsigned used_mask = 0;
        int j0 = M1;
        __syncwarp();

        while (true) {
            int i0 = p[j0];
            if (i0 == -1) break;
            if (j0 < M1 && (j0 & 31) == lane) used_mask |= 1u << (j0 >> 5);
            float ui0 = u[i0];
            unsigned long long local = ~0ull;
            #pragma unroll
            for (int k = 0; k < 10; k++) {
                int j = lane + 32 * k;
                if (j < M1 && !((used_mask >> k) & 1u)) {
                    float cur = cost[i0 * M1 + j] - ui0 - v_r[k];
                    if (cur < minv_r[k]) { minv_r[k] = cur; way[j] = j0; }
                    unsigned bits = __float_as_uint(minv_r[k]);
                    unsigned key = (bits & 0x80000000u) ? ~bits : (bits | 0x80000000u);
                    unsigned long long cand = ((unsigned long long)key << 32) | (unsigned)j;
                    if (cand < local) local = cand;
                }
            }
            #pragma unroll
            for (int o = 16; o; o >>= 1) {
                unsigned long long oth = __shfl_xor_sync(0xffffffffu, local, o);
                if (oth < local) local = oth;
            }
            int j1 = (int)(local & 0xffffffffu);
            unsigned key = (unsigned)(local >> 32);
            unsigned bits2 = (key & 0x80000000u) ? (key ^ 0x80000000u) : ~key;
            float delta = __uint_as_float(bits2);

            #pragma unroll
            for (int k = 0; k < 10; k++) {
                int j = lane + 32 * k;
                if (j < M1) {
                    if ((used_mask >> k) & 1u) { v_r[k] -= delta; u[p[j]] += delta; }
                    else minv_r[k] -= delta;
                }
            }
            if (lane == 0) u[irow] += delta;
            j0 = j1;
            __syncwarp();
        }

        if (lane == 0) {
            int jj = j0;
            while (jj != M1) { int jn = way[jj]; p[jj] = p[jn]; jj = jn; }
        }
        __syncwarp();
    }

    // ---- emit pred_idx / gt_idx (sorted by assigned column) ----
    #pragma unroll
    for (int k = 0; k < 10; k++) {
        int j = lane + 32 * k;
        if (j < M1) { int r = p[j]; if (r >= 0) qrow[r] = j; }
    }
    __syncwarp();
    for (int r = lane; r < N1; r += 32) {
        int qi = qrow[r];
        int rank = 0;
        #pragma unroll 10
        for (int k2 = 0; k2 < N1; k2++) rank += (qrow[k2] < qi);
        out[b * MM + rank] = (float)qi;            // pred_idx
        out[NT + b * MM + rank] = (float)r;        // gt_idx
    }
}

// ---------------------------------------------------------------------------
extern "C" void kernel_launch(void* const* d_in, const int* in_sizes, int n_in,
                              void* d_out, int out_size) {
    const float* pred_logits = (const float*)d_in[0];
    const float* pred_boxes  = (const float*)d_in[1];
    const int*   tgt_labels  = (const int*)d_in[2];
    const float* tgt_boxes   = (const float*)d_in[3];
    float* out = (float*)d_out;
    float* Cout = out + 2 * NT;   // C after pred_idx (1600) + gt_idx (1600)

    // A: softmax
    {
        int threads = 256;
        int blocks = (NP * 32 + threads - 1) / threads;
        softmax_kernel<<<blocks, threads>>>(pred_logits);
    }
    // B: cost matrix (+diag sidecar)
    {
        dim3 block(16, 16);
        dim3 grid(NT / 64, NP / 16);
        cost_kernel<<<grid, block>>>(pred_boxes, tgt_labels, tgt_boxes, Cout);
    }
    // C: hungarian (warp JV + greedy init), reads g_diag
    {
        size_t smem = (size_t)(N1 * M1 + (N1 + 1)) * sizeof(float)
                    + (size_t)((M1 + 1) + M1 + N1 + N1) * sizeof(int);
        cudaFuncSetAttribute(hungarian_kernel,
                             cudaFuncAttributeMaxDynamicSharedMemorySize, (int)smem);
        hungarian_kernel<<<BB, 256, smem>>>(out);
    }
}

// round 14
// speedup vs baseline: 2.7220x; 2.7220x over previous
#include <cuda_runtime.h>
#include <float.h>

#define BB 32
#define QQ 300
#define NCLS 92
#define MM 50
#define NP (BB*QQ)      // 9600 pred rows
#define NT (BB*MM)      // 1600 target cols
#define M1 300          // m (columns in hungarian)
#define N1 50           // n (rows in hungarian)

// Normalized softmax probabilities, 9600 x 92 (3.53 MB scratch)
__device__ float g_probs[NP * NCLS];
// Dense per-batch diagonal cost tiles [b][i(target 0..49)][j(pred 0..299)]
__device__ float g_diag[BB * N1 * M1];

// ---------------------------------------------------------------------------
// ordered-float <-> uint monotone key
// ---------------------------------------------------------------------------
__device__ __forceinline__ unsigned f2key(float f) {
    unsigned b = __float_as_uint(f);
    return (b & 0x80000000u) ? ~b : (b | 0x80000000u);
}
__device__ __forceinline__ float key2f(unsigned k) {
    unsigned b = (k & 0x80000000u) ? (k ^ 0x80000000u) : ~k;
    return __uint_as_float(b);
}
__device__ __forceinline__ unsigned redux_min_u32(unsigned x) {
    unsigned r;
    asm volatile("redux.sync.min.u32 %0, %1, 0xffffffff;" : "=r"(r) : "r"(x));
    return r;
}
// warp argmin over (key, j); ties -> smallest j (matches reference argmin)
__device__ __forceinline__ void warp_argmin(unsigned key, int j,
                                            unsigned& mink, int& minj) {
    unsigned mk = redux_min_u32(key);
    unsigned cj = (key == mk) ? (unsigned)j : 0xffffffffu;
    unsigned mj = redux_min_u32(cj);
    mink = mk; minj = (int)mj;
}

// ---------------------------------------------------------------------------
// shared cost formula
// ---------------------------------------------------------------------------
__device__ __forceinline__ float cost_pair(
    float pcx, float pcy, float pw, float ph,
    float ax0, float ay0, float ax1, float ay1, float areaA, float cc,
    float tcx, float tcy, float tw, float th,
    float bx0, float by0, float bx1, float by1, float areaB) {
    float cb = fabsf(pcx - tcx) + fabsf(pcy - tcy)
             + fabsf(pw - tw)   + fabsf(ph - th);
    float iw = fmaxf(fminf(ax1, bx1) - fmaxf(ax0, bx0), 0.f);
    float ih = fmaxf(fminf(ay1, by1) - fmaxf(ay0, by0), 0.f);
    float inter = iw * ih;
    float uni = areaA + areaB - inter;
    float iou = __fdividef(inter, uni);
    float ew = fmaxf(ax1, bx1) - fminf(ax0, bx0);
    float eh = fmaxf(ay1, by1) - fminf(ay0, by0);
    float areaE = ew * eh;
    float giou = iou - __fdividef(areaE - uni, areaE);
    return cc + 5.0f * cb - 2.0f * giou;
}

// ---------------------------------------------------------------------------
// Kernel A: row softmax of logits. One warp per row.
// ---------------------------------------------------------------------------
__global__ void softmax_kernel(const float* __restrict__ logits) {
    int warp = (blockIdx.x * blockDim.x + threadIdx.x) >> 5;
    int lane = threadIdx.x & 31;
    if (warp >= NP) return;
    const float* row = logits + (size_t)warp * NCLS;
    float x0 = row[lane];
    float x1 = row[lane + 32];
    float x2 = (lane < NCLS - 64) ? row[lane + 64] : -FLT_MAX;
    float mx = fmaxf(fmaxf(x0, x1), x2);
    #pragma unroll
    for (int o = 16; o; o >>= 1) mx = fmaxf(mx, __shfl_xor_sync(0xffffffffu, mx, o));
    float e0 = __expf(x0 - mx), e1 = __expf(x1 - mx);
    float e2 = (lane < NCLS - 64) ? __expf(x2 - mx) : 0.f;
    float s = e0 + e1 + e2;
    #pragma unroll
    for (int o = 16; o; o >>= 1) s += __shfl_xor_sync(0xffffffffu, s, o);
    float inv = __fdividef(1.f, s);
    float* prow = g_probs + (size_t)warp * NCLS;
    prow[lane] = e0 * inv;
    prow[lane + 32] = e1 * inv;
    if (lane < NCLS - 64) prow[lane + 64] = e2 * inv;
}

// ---------------------------------------------------------------------------
// Kernel D: diagonal cost tiles only (32 batches x 50 x 300 = 480K entries).
// grid 64 x 256 threads; entry (b,i,j): pred b*300+j vs target b*50+i.
// ---------------------------------------------------------------------------
__global__ void diag_kernel(const float* __restrict__ pred_boxes,
                            const int*   __restrict__ tgt_labels,
                            const float* __restrict__ tgt_boxes) {
    int gid = blockIdx.x * blockDim.x + threadIdx.x;
    int nthr = gridDim.x * blockDim.x;
    for (int idx = gid; idx < BB * N1 * M1; idx += nthr) {
        int b = idx / (N1 * M1);
        int rem = idx - b * N1 * M1;
        int i = rem / M1;          // target local
        int j = rem - i * M1;      // pred local
        int gp = b * QQ + j;
        int gt = b * MM + i;
        const float* pb = pred_boxes + (size_t)gp * 4;
        float pcx = pb[0], pcy = pb[1], pw = pb[2], ph = pb[3];
        float ax0 = pcx - 0.5f * pw, ay0 = pcy - 0.5f * ph;
        float ax1 = pcx + 0.5f * pw, ay1 = pcy + 0.5f * ph;
        float areaA = (ax1 - ax0) * (ay1 - ay0);
        const float* tb = tgt_boxes + (size_t)gt * 4;
        float tcx = tb[0], tcy = tb[1], tw = tb[2], th = tb[3];
        float bx0 = tcx - 0.5f * tw, by0 = tcy - 0.5f * th;
        float bx1 = tcx + 0.5f * tw, by1 = tcy + 0.5f * th;
        float areaB = (bx1 - bx0) * (by1 - by0);
        float cc = -g_probs[(size_t)gp * NCLS + tgt_labels[gt]];
        g_diag[idx] = cost_pair(pcx, pcy, pw, ph, ax0, ay0, ax1, ay1, areaA, cc,
                                tcx, tcy, tw, th, bx0, by0, bx1, by1, areaB);
    }
}

// ---------------------------------------------------------------------------
// Kernel B: full cross cost matrix C[9600][1600]  (exact R7 structure).
// Tile: 16 preds x 64 targets per block; block (64,4), each thread 4 preds.
// ---------------------------------------------------------------------------
__global__ void cost_kernel(const float* __restrict__ pred_boxes,
                            const int*   __restrict__ tgt_labels,
                            const float* __restrict__ tgt_boxes,
                            float* __restrict__ Cout) {
    __shared__ float s_probs[16 * NCLS];
    __shared__ float s_pcx[16][4];
    __shared__ float s_pxy[16][4];
    __shared__ float s_parea[16];
    __shared__ float s_tcx[64][4];
    __shared__ float s_txy[64][4];
    __shared__ float s_tarea[64];
    __shared__ int   s_tl[64];

    int tid = threadIdx.y * 64 + threadIdx.x;
    int p0 = blockIdx.x * 16;
    int t0 = blockIdx.y * 64;

    for (int i = tid; i < 16 * NCLS; i += 256) {
        int pp = i / NCLS, c = i - pp * NCLS;
        s_probs[pp * NCLS + c] = g_probs[(size_t)(p0 + pp) * NCLS + c];
    }
    if (tid < 16) {
        const float* b = pred_boxes + (size_t)(p0 + tid) * 4;
        float cx = b[0], cy = b[1], w = b[2], h = b[3];
        s_pcx[tid][0] = cx; s_pcx[tid][1] = cy; s_pcx[tid][2] = w; s_pcx[tid][3] = h;
        float x0 = cx - 0.5f * w, y0 = cy - 0.5f * h;
        float x1 = cx + 0.5f * w, y1 = cy + 0.5f * h;
        s_pxy[tid][0] = x0; s_pxy[tid][1] = y0; s_pxy[tid][2] = x1; s_pxy[tid][3] = y1;
        s_parea[tid] = (x1 - x0) * (y1 - y0);
    }
    if (tid < 64) {
        const float* b = tgt_boxes + (size_t)(t0 + tid) * 4;
        float cx = b[0], cy = b[1], w = b[2], h = b[3];
        s_tcx[tid][0] = cx; s_tcx[tid][1] = cy; s_tcx[tid][2] = w; s_tcx[tid][3] = h;
        float x0 = cx - 0.5f * w, y0 = cy - 0.5f * h;
        float x1 = cx + 0.5f * w, y1 = cy + 0.5f * h;
        s_txy[tid][0] = x0; s_txy[tid][1] = y0; s_txy[tid][2] = x1; s_txy[tid][3] = y1;
        s_tarea[tid] = (x1 - x0) * (y1 - y0);
        s_tl[tid] = tgt_labels[t0 + tid];
    }
    __syncthreads();

    int tx = threadIdx.x;
    int lab = s_tl[tx];
    float tcx = s_tcx[tx][0], tcy = s_tcx[tx][1], tw = s_tcx[tx][2], th = s_tcx[tx][3];
    float bx0 = s_txy[tx][0], by0 = s_txy[tx][1], bx1 = s_txy[tx][2], by1 = s_txy[tx][3];
    float areaB = s_tarea[tx];
    int col = t0 + tx;

    #pragma unroll
    for (int k = 0; k < 4; k++) {
        int pp = threadIdx.y + k * 4;
        float cc = -s_probs[pp * NCLS + lab];
        float c = cost_pair(s_pcx[pp][0], s_pcx[pp][1], s_pcx[pp][2], s_pcx[pp][3],
                            s_pxy[pp][0], s_pxy[pp][1], s_pxy[pp][2], s_pxy[pp][3],
                            s_parea[pp], cc,
                            tcx, tcy, tw, th, bx0, by0, bx1, by1, areaB);
        Cout[(size_t)(p0 + pp) * NT + col] = c;
    }
}

// ---------------------------------------------------------------------------
// Kernel C: warp-level Jonker-Volgenant with greedy dual initialization.
// Triggers PDL completion at entry so cost_kernel can overlap.
// ---------------------------------------------------------------------------
__global__ void hungarian_kernel(float* __restrict__ out) {
    if (threadIdx.x == 0) cudaTriggerProgrammaticLaunchCompletion();

    extern __shared__ float smem[];
    float* cost = smem;                 // 50*300
    float* u    = cost + N1 * M1;       // 51
    int*   p    = (int*)(u + (N1 + 1)); // 301
    int*   way  = p + (M1 + 1);         // 300
    int*   pend = way + M1;             // 50
    int*   qrow = pend + N1;            // 50
    __shared__ int s_npend;

    int b = blockIdx.x;
    int tid = threadIdx.x;

    const float* gd = g_diag + (size_t)b * N1 * M1;
    for (int idx = tid; idx < N1 * M1; idx += 256) cost[idx] = gd[idx];
    for (int idx = tid; idx < N1 + 1; idx += 256) u[idx] = 0.f;
    for (int idx = tid; idx <= M1; idx += 256) p[idx] = -1;
    if (tid == 0) s_npend = 0;
    __syncthreads();
    if (tid >= 32) return;   // warp 0 solves alone

    int lane = tid;
    float v_r[10], minv_r[10];
    #pragma unroll
    for (int k = 0; k < 10; k++) v_r[k] = 0.f;

    // ---- greedy init: u[i] = row min; assign row to argmin col if free ----
    for (int i = 0; i < N1; ++i) {
        unsigned lkey = 0xffffffffu; int lj = 0x7fffffff;
        #pragma unroll
        for (int k = 0; k < 10; k++) {
            int j = lane + 32 * k;
            if (j < M1) {
                unsigned key = f2key(cost[i * M1 + j]);
                if (key < lkey) { lkey = key; lj = j; }
            }
        }
        unsigned mink; int jstar;
        warp_argmin(lkey, lj, mink, jstar);
        if (lane == 0) {
            u[i] = key2f(mink);
            if (p[jstar] == -1) p[jstar] = i;
            else { pend[s_npend] = i; s_npend = s_npend + 1; }
        }
        __syncwarp();
    }
    int npend = s_npend;

    // ---- Dijkstra augmenting paths for the few unassigned rows ----
    for (int t = 0; t < npend; ++t) {
        int irow = pend[t];
        if (lane == 0) p[M1] = irow;
        #pragma unroll
        for (int k = 0; k < 10; k++) minv_r[k] = FLT_MAX;
        unsigned used_mask = 0;
        int j0 = M1;
        __syncwarp();

        while (true) {
            int i0 = p[j0];
            if (i0 == -1) break;
            if (j0 < M1 && (j0 & 31) == lane) used_mask |= 1u << (j0 >> 5);
            float ui0 = u[i0];
            unsigned lkey = 0xffffffffu; int lj = 0x7fffffff;
            #pragma unroll
            for (int k = 0; k < 10; k++) {
                int j = lane + 32 * k;
                if (j < M1 && !((used_mask >> k) & 1u)) {
                    float cur = cost[i0 * M1 + j] - ui0 - v_r[k];
                    if (cur < minv_r[k]) { minv_r[k] = cur; way[j] = j0; }
                    unsigned key = f2key(minv_r[k]);
                    if (key < lkey) { lkey = key; lj = j; }
                }
            }
            unsigned mink; int j1;
            warp_argmin(lkey, lj, mink, j1);
            float delta = key2f(mink);

            #pragma unroll
            for (int k = 0; k < 10; k++) {
                int j = lane + 32 * k;
                if (j < M1) {
                    if ((used_mask >> k) & 1u) { v_r[k] -= delta; u[p[j]] += delta; }
                    else minv_r[k] -= delta;
                }
            }
            if (lane == 0) u[irow] += delta;
            j0 = j1;
            __syncwarp();
        }

        if (lane == 0) {
            int jj = j0;
            while (jj != M1) { int jn = way[jj]; p[jj] = p[jn]; jj = jn; }
        }
        __syncwarp();
    }

    // ---- emit pred_idx / gt_idx (sorted by assigned column) ----
    #pragma unroll
    for (int k = 0; k < 10; k++) {
        int j = lane + 32 * k;
        if (j < M1) { int r = p[j]; if (r >= 0) qrow[r] = j; }
    }
    __syncwarp();
    for (int r = lane; r < N1; r += 32) {
        int qi = qrow[r];
        int rank = 0;
        #pragma unroll 10
        for (int k2 = 0; k2 < N1; k2++) rank += (qrow[k2] < qi);
        out[b * MM + rank] = (float)qi;            // pred_idx
        out[NT + b * MM + rank] = (float)r;        // gt_idx
    }
}

// ---------------------------------------------------------------------------
extern "C" void kernel_launch(void* const* d_in, const int* in_sizes, int n_in,
                              void* d_out, int out_size) {
    const float* pred_logits = (const float*)d_in[0];
    const float* pred_boxes  = (const float*)d_in[1];
    const int*   tgt_labels  = (const int*)d_in[2];
    const float* tgt_boxes   = (const float*)d_in[3];
    float* out = (float*)d_out;
    float* Cout = out + 2 * NT;   // C after pred_idx (1600) + gt_idx (1600)

    // A: softmax
    {
        int threads = 256;
        int blocks = (NP * 32 + threads - 1) / threads;
        softmax_kernel<<<blocks, threads>>>(pred_logits);
    }
    // D: diagonal tiles (hungarian's input)
    diag_kernel<<<64, 256>>>(pred_boxes, tgt_labels, tgt_boxes);

    // C: hungarian (32 blocks; triggers PDL completion at entry)
    {
        size_t smem = (size_t)(N1 * M1 + (N1 + 1)) * sizeof(float)
                    + (size_t)((M1 + 1) + M1 + N1 + N1) * sizeof(int);
        cudaFuncSetAttribute(hungarian_kernel,
                             cudaFuncAttributeMaxDynamicSharedMemorySize, (int)smem);
        hungarian_kernel<<<BB, 256, smem>>>(out);
    }
    // B: full cost matrix, allowed to start while hungarian still runs (PDL)
    {
        cudaLaunchConfig_t cfg = {};
        cfg.gridDim = dim3(NP / 16, NT / 64, 1);
        cfg.blockDim = dim3(64, 4, 1);
        cfg.dynamicSmemBytes = 0;
        cfg.stream = 0;
        cudaLaunchAttribute attr[1];
        attr[0].id = cudaLaunchAttributeProgrammaticStreamSerialization;
        attr[0].val.programmaticStreamSerializationAllowed = 1;
        cfg.attrs = attr;
        cfg.numAttrs = 1;
        cudaLaunchKernelEx(&cfg, cost_kernel,
                           pred_boxes, tgt_labels, tgt_boxes, Cout);
    }
}